// round 14
// baseline (speedup 1.0000x reference)
#include <cuda_runtime.h>

#define B_   16
#define T_   200
#define U1_  101
#define U_   100
#define V_   512
#define ND_  300          /* time-diagonals: d = t+u in [0, 299] */
#define DW_  104          /* padded diagonal width (u slots), 26 float4 */
#define DW4_ 26
#define PH2_ 76           /* diagonal rows staged per phase (4 phases) */
#define NPH_ 4
#define PAD_ 128          /* per-region guard pad (floats) */
#define RS_  (PH2_ * DW_ + PAD_)   /* region stride: 8032 floats */
#define NEGV   (-1e30f)
#define LOG2E_ 1.4426950408889634f
#define LN2_   0.6931471805599453f

// Diagonal-major scratch (natural-log): [b][d][u]. emitD shifted (+1 in u) so
// cell (d,u)'s deps both sit at row d-1, slot u. Dead slots = stale garbage;
// the staging mask replaces them with NEGV by pure coordinate tests.
__device__ float g_blankD[B_ * ND_ * DW_];
__device__ float g_emitD [B_ * ND_ * DW_];
__device__ volatile float g_cost[B_];
__device__ int   g_done = 0;

__device__ __forceinline__ float ex2f_(float x) {
    float r; asm("ex2.approx.ftz.f32 %0, %1;" : "=f"(r) : "f"(x)); return r;
}
__device__ __forceinline__ float lg2f_(float x) {
    float r; asm("lg2.approx.ftz.f32 %0, %1;" : "=f"(r) : "f"(x)); return r;
}

// ---------------------------------------------------------------------------
// Kernel 1: per-row log-softmax stats. One warp per live (b,t,u) row.
// ---------------------------------------------------------------------------
__global__ void __launch_bounds__(256) rnnt_softmax_kernel(
    const float* __restrict__ acts,
    const int*   __restrict__ labels,
    const int*   __restrict__ act_lens,
    const int*   __restrict__ label_lens)
{
    const int warp = (blockIdx.x * blockDim.x + threadIdx.x) >> 5;
    const int lane = threadIdx.x & 31;
    const int R = B_ * T_ * U1_;
    if (warp >= R) return;

    const int u = warp % U1_;
    const int t = (warp / U1_) % T_;
    const int b = warp / (T_ * U1_);

    const int alen = act_lens[b];
    const int llen = label_lens[b];
    if (t >= alen || u > llen) return;

    const float4* __restrict__ p =
        reinterpret_cast<const float4*>(acts + (size_t)warp * V_);
    float4 v0 = __ldcs(p + lane);
    float4 v1 = __ldcs(p + lane + 32);
    float4 v2 = __ldcs(p + lane + 64);
    float4 v3 = __ldcs(p + lane + 96);

    float m = fmaxf(fmaxf(fmaxf(v0.x, v0.y), fmaxf(v0.z, v0.w)),
                    fmaxf(fmaxf(v1.x, v1.y), fmaxf(v1.z, v1.w)));
    m = fmaxf(m, fmaxf(fmaxf(fmaxf(v2.x, v2.y), fmaxf(v2.z, v2.w)),
                       fmaxf(fmaxf(v3.x, v3.y), fmaxf(v3.z, v3.w))));
    #pragma unroll
    for (int off = 16; off > 0; off >>= 1)
        m = fmaxf(m, __shfl_xor_sync(0xffffffffu, m, off));

    float s = __expf(v0.x - m) + __expf(v0.y - m) + __expf(v0.z - m) + __expf(v0.w - m)
            + __expf(v1.x - m) + __expf(v1.y - m) + __expf(v1.z - m) + __expf(v1.w - m)
            + __expf(v2.x - m) + __expf(v2.y - m) + __expf(v2.z - m) + __expf(v2.w - m)
            + __expf(v3.x - m) + __expf(v3.y - m) + __expf(v3.z - m) + __expf(v3.w - m);
    #pragma unroll
    for (int off = 16; off > 0; off >>= 1)
        s += __shfl_xor_sync(0xffffffffu, s, off);

    const float lse = m + __logf(s);
    const float blank_logit = __shfl_sync(0xffffffffu, v0.x, 0);

    int lbl = 0;
    if (u < U_) lbl = labels[b * U_ + u];
    const int j   = lbl >> 2;
    const int src = j & 31;
    const int k   = j >> 5;
    const int c   = lbl & 3;
    float4 sel = (k == 0) ? v0 : (k == 1) ? v1 : (k == 2) ? v2 : v3;
    float cand = (c == 0) ? sel.x : (c == 1) ? sel.y : (c == 2) ? sel.z : sel.w;
    const float label_logit = __shfl_sync(0xffffffffu, cand, src);

    if (lane == 0) {
        const int d    = t + u;
        const int base = b * ND_ * DW_ + d * DW_;
        g_blankD[base + u] = blank_logit - lse;
        if (u < llen)
            g_emitD[base + u + 1] = label_logit - lse;
    }
}

// ---------------------------------------------------------------------------
// Masked staging: NEGV for coordinate-invalid slots; valid -> log2 domain.
// ---------------------------------------------------------------------------
__device__ __forceinline__ void stage_row4(
    float4 xb, float4 xe, int r, int v0, int alen, int llen,
    float4* outB, float4* outE)
{
    float bb[4] = { xb.x, xb.y, xb.z, xb.w };
    float ee[4] = { xe.x, xe.y, xe.z, xe.w };
    #pragma unroll
    for (int k = 0; k < 4; ++k) {
        const int v = v0 + k;
        const bool bv = (v <= llen) && (v <= r)     && (r - v     <= alen - 1);
        const bool ev = (v >= 1) && (v <= llen) && (v <= r + 1) && (r - v + 1 <= alen - 1);
        bb[k] = bv ? (bb[k] * LOG2E_) : NEGV;
        ee[k] = ev ? (ee[k] * LOG2E_) : NEGV;
    }
    *outB = make_float4(bb[0], bb[1], bb[2], bb[3]);
    *outE = make_float4(ee[0], ee[1], ee[2], ee[3]);
}

// One batch's per-diagonal update (4 cells), log2 domain.
__device__ __forceinline__ void dp_step(
    float am1, const float4& bl, const float4& em,
    float& a0, float& a1, float& a2, float& a3)
{
    const float t0 = a0 + bl.x, t1 = a1 + bl.y, t2 = a2 + bl.z, t3 = a3 + bl.w;
    const float l0 = am1 + em.x, l1 = a0 + em.y, l2 = a1 + em.z, l3 = a2 + em.w;
    const float x0 = fmaxf(t0, l0), x1 = fmaxf(t1, l1);
    const float x2 = fmaxf(t2, l2), x3 = fmaxf(t3, l3);
    const float d0 = fminf(t0, l0) - x0, d1 = fminf(t1, l1) - x1;
    const float d2 = fminf(t2, l2) - x2, d3 = fminf(t3, l3) - x3;
    const float g0 = ex2f_(d0), g1 = ex2f_(d1);
    const float g2 = ex2f_(d2), g3 = ex2f_(d3);
    a0 = x0 + lg2f_(1.0f + g0);
    a1 = x1 + lg2f_(1.0f + g1);
    a2 = x2 + lg2f_(1.0f + g2);
    a3 = x3 + lg2f_(1.0f + g3);
}

// ---------------------------------------------------------------------------
// Kernel 2: forward DP — warp 0 runs TWO batches interleaved (independent
// recurrence chains fill each other's stall cycles). 8 blocks of 2 batches.
// 4 staging phases of 76 diagonal rows; predicated capture at d == dstar_k.
// ---------------------------------------------------------------------------
__global__ void __launch_bounds__(128, 1) rnnt_dp_kernel(
    const int* __restrict__ act_lens,
    const int* __restrict__ label_lens,
    float* __restrict__ out)
{
    extern __shared__ float sm[];
    float* B0s = sm;
    float* E0s = sm + RS_;
    float* B1s = sm + 2 * RS_;
    float* E1s = sm + 3 * RS_;

    const int bid  = blockIdx.x;          // 0..7
    const int b0   = 2 * bid;
    const int b1   = 2 * bid + 1;
    const int tid  = threadIdx.x;
    const int lane = tid & 31;

    const int alen0 = act_lens[b0],  llen0 = label_lens[b0];
    const int alen1 = act_lens[b1],  llen1 = label_lens[b1];
    const int dstar0 = (alen0 - 1) + llen0;
    const int dstar1 = (alen1 - 1) + llen1;
    const int dmax   = (dstar0 > dstar1) ? dstar0 : dstar1;

    const float4* gB0 = reinterpret_cast<const float4*>(g_blankD + b0 * ND_ * DW_);
    const float4* gE0 = reinterpret_cast<const float4*>(g_emitD  + b0 * ND_ * DW_);
    const float4* gB1 = reinterpret_cast<const float4*>(g_blankD + b1 * ND_ * DW_);
    const float4* gE1 = reinterpret_cast<const float4*>(g_emitD  + b1 * ND_ * DW_);
    float4* sB0 = reinterpret_cast<float4*>(B0s);
    float4* sE0 = reinterpret_cast<float4*>(E0s);
    float4* sB1 = reinterpret_cast<float4*>(B1s);
    float4* sE1 = reinterpret_cast<float4*>(E1s);

    const int ubase = lane << 2;

    float a00 = 0.f, a01 = NEGV, a02 = NEGV, a03 = NEGV;   // batch 0 alpha2
    float a10 = 0.f, a11 = NEGV, a12 = NEGV, a13 = NEGV;   // batch 1 alpha2
    a00 = (lane == 0) ? 0.0f : NEGV;
    a10 = (lane == 0) ? 0.0f : NEGV;
    float res0 = NEGV, res1 = NEGV;
    const int slot0 = llen0 & 3, slot1 = llen1 & 3;

    #pragma unroll 1
    for (int p = 0; p < NPH_; ++p) {
        const int r0 = p * PH2_;
        if (r0 + 1 > dmax) break;                       // uniform across block
        const int nrows = ((ND_ - 1) - r0 < PH2_) ? ((ND_ - 1) - r0) : PH2_;

        // Stage rows [r0, r0+nrows) for both batches (all 128 threads).
        {
            const int n4 = nrows * DW4_;
            for (int i = tid; i < n4; i += 128) {
                const int rr = i / DW4_;
                const int cc = i - rr * DW4_;
                const int r  = r0 + rr;
                const int v0 = cc * 4;
                const int gi = r * DW4_ + cc;
                stage_row4(gB0[gi], gE0[gi], r, v0, alen0, llen0, &sB0[i], &sE0[i]);
                stage_row4(gB1[gi], gE1[gi], r, v0, alen1, llen1, &sB1[i], &sE1[i]);
            }
        }
        __syncthreads();

        if (tid < 32) {
            const int dlo = r0 + 1;
            const int dhi = (r0 + nrows < dmax) ? (r0 + nrows) : dmax;
            int off = ubase;
            float4 bl0 = *reinterpret_cast<const float4*>(B0s + off);
            float4 em0 = *reinterpret_cast<const float4*>(E0s + off);
            float4 bl1 = *reinterpret_cast<const float4*>(B1s + off);
            float4 em1 = *reinterpret_cast<const float4*>(E1s + off);
            for (int d = dlo; d <= dhi; ++d) {
                const float am10 = __shfl_up_sync(0xffffffffu, a03, 1);
                const float am11 = __shfl_up_sync(0xffffffffu, a13, 1);
                const float4 cb0 = bl0, ce0 = em0, cb1 = bl1, ce1 = em1;
                off += DW_;                              // prefetch next row
                bl0 = *reinterpret_cast<const float4*>(B0s + off);
                em0 = *reinterpret_cast<const float4*>(E0s + off);
                bl1 = *reinterpret_cast<const float4*>(B1s + off);
                em1 = *reinterpret_cast<const float4*>(E1s + off);
                dp_step(am10, cb0, ce0, a00, a01, a02, a03);
                dp_step(am11, cb1, ce1, a10, a11, a12, a13);
                if (d == dstar0)
                    res0 = (slot0 == 0) ? a00 : (slot0 == 1) ? a01
                         : (slot0 == 2) ? a02 : a03;
                if (d == dstar1)
                    res1 = (slot1 == 0) ? a10 : (slot1 == 1) ? a11
                         : (slot1 == 2) ? a12 : a13;
            }
        }
        __syncthreads();
    }

    if (tid < 32) {
        const float r0v = __shfl_sync(0xffffffffu, res0, llen0 >> 2);
        const float r1v = __shfl_sync(0xffffffffu, res1, llen1 >> 2);
        if (lane == 0) {
            const float fb0 = g_blankD[b0 * ND_ * DW_ + dstar0 * DW_ + llen0];
            const float fb1 = g_blankD[b1 * ND_ * DW_ + dstar1 * DW_ + llen1];
            g_cost[b0] = -(r0v * LN2_ + fb0);
            g_cost[b1] = -(r1v * LN2_ + fb1);
            __threadfence();
            const int prev = atomicAdd(&g_done, 1);
            if (prev == (B_ / 2) - 1) {
                __threadfence();
                float s = 0.0f;
                #pragma unroll
                for (int i = 0; i < B_; ++i) s += g_cost[i];
                out[0] = s / (float)B_;
                g_done = 0;            // reset for next graph replay
            }
        }
    }
}

// ---------------------------------------------------------------------------
extern "C" void kernel_launch(void* const* d_in, const int* in_sizes, int n_in,
                              void* d_out, int out_size)
{
    const float* acts       = (const float*)d_in[0];
    const int*   labels     = (const int*)  d_in[1];
    const int*   act_lens   = (const int*)  d_in[2];
    const int*   label_lens = (const int*)  d_in[3];
    float*       out        = (float*)      d_out;

    // Kernel 1: log-softmax stats over live rows only.
    const int rows   = B_ * T_ * U1_;
    const int wpb    = 8;
    const int blocks = (rows + wpb - 1) / wpb;
    rnnt_softmax_kernel<<<blocks, wpb * 32>>>(acts, labels, act_lens, label_lens);

    // Kernel 2: DP (2 batches per block) + finalize.
    const size_t smemBytes = (size_t)4 * RS_ * sizeof(float);   // 128,512 B
    cudaFuncSetAttribute(rnnt_dp_kernel,
                         cudaFuncAttributeMaxDynamicSharedMemorySize,
                         (int)smemBytes);
    rnnt_dp_kernel<<<B_ / 2, 128, smemBytes>>>(act_lens, label_lens, out);
}

// round 15
// speedup vs baseline: 1.2316x; 1.2316x over previous
#include <cuda_runtime.h>

#define B_   16
#define T_   200
#define U1_  101
#define U_   100
#define V_   512
#define ND_  300          /* time-diagonals: d = t+u in [0, 299] */
#define DW_  104          /* padded diagonal width (u slots), 26 float4 */
#define DW4_ 26
#define PH_  19           /* diagonal rows staged per phase */
#define NPH_ 16           /* 16*19 = 304 >= 299 */
#define PAD_ 128          /* guard pad (floats): prefetch + lane overread */
#define RS_  (PH_ * DW_ + PAD_)   /* region stride: 2104 floats */
#define NDPB_ 16          /* DP blocks (first in grid) */
#define NEGV   (-1e30f)
#define LOG2E_ 1.4426950408889634f
#define LN2_   0.6931471805599453f

// Diagonal-major scratch (natural-log): [b][d][u]. emitD shifted (+1 in u) so
// cell (d,u)'s deps both sit at row d-1, slot u. Dead slots = stale garbage;
// the DP staging mask replaces them with NEGV by pure coordinate tests.
__device__ float g_blankD[B_ * ND_ * DW_];
__device__ float g_emitD [B_ * ND_ * DW_];
__device__ int   g_cnt   [B_ * ND_];      // rows completed per (b, diagonal)
__device__ volatile float g_cost[B_];
__device__ int   g_done;

__device__ __forceinline__ float ex2f_(float x) {
    float r; asm("ex2.approx.ftz.f32 %0, %1;" : "=f"(r) : "f"(x)); return r;
}
__device__ __forceinline__ float lg2f_(float x) {
    float r; asm("lg2.approx.ftz.f32 %0, %1;" : "=f"(r) : "f"(x)); return r;
}

// Live-cell count on diagonal r for batch (alen, llen):
// u in [max(0, r-alen+1), min(llen, r)].
__device__ __forceinline__ int live_count(int r, int alen, int llen) {
    const int hi = (llen < r) ? llen : r;
    const int lo = (r - alen + 1 > 0) ? (r - alen + 1) : 0;
    return hi - lo + 1;             // may be <= 0 for r > dstar
}

// ---------------------------------------------------------------------------
// Kernel 0: zero the sync state (counters + done flag) for each graph replay.
// ---------------------------------------------------------------------------
__global__ void rnnt_init_kernel()
{
    const int i = blockIdx.x * blockDim.x + threadIdx.x;
    if (i < B_ * ND_) g_cnt[i] = 0;
    if (i == 0) g_done = 0;
}

// ---------------------------------------------------------------------------
// Masked staging: NEGV for coordinate-invalid slots; valid -> log2 domain.
// ---------------------------------------------------------------------------
__device__ __forceinline__ void stage_row4(
    float4 xb, float4 xe, int r, int v0, int alen, int llen,
    float4* outB, float4* outE)
{
    float bb[4] = { xb.x, xb.y, xb.z, xb.w };
    float ee[4] = { xe.x, xe.y, xe.z, xe.w };
    #pragma unroll
    for (int k = 0; k < 4; ++k) {
        const int v = v0 + k;
        const bool bv = (v <= llen) && (v <= r)     && (r - v     <= alen - 1);
        const bool ev = (v >= 1) && (v <= llen) && (v <= r + 1) && (r - v + 1 <= alen - 1);
        bb[k] = bv ? (bb[k] * LOG2E_) : NEGV;
        ee[k] = ev ? (ee[k] * LOG2E_) : NEGV;
    }
    *outB = make_float4(bb[0], bb[1], bb[2], bb[3]);
    *outE = make_float4(ee[0], ee[1], ee[2], ee[3]);
}

// ---------------------------------------------------------------------------
// Fused kernel.  Blocks [0, NDPB_): persistent per-batch DP consumers.
// Blocks [NDPB_, ...): log-softmax producers in DIAGONAL-MAJOR order, so
// diagonal d (all batches) completes at ~d/300 of softmax time.
// ---------------------------------------------------------------------------
__global__ void __launch_bounds__(256) rnnt_fused_kernel(
    const float* __restrict__ acts,
    const int*   __restrict__ labels,
    const int*   __restrict__ act_lens,
    const int*   __restrict__ label_lens,
    float* __restrict__ out)
{
    // ================= DP consumer blocks =================
    if (blockIdx.x < NDPB_) {
        __shared__ float Bs[RS_];
        __shared__ float Es[RS_];

        const int b    = blockIdx.x;
        const int tid  = threadIdx.x;
        const int lane = tid & 31;

        const int alen  = act_lens[b];
        const int llen  = label_lens[b];
        const int dstar = (alen - 1) + llen;      // in [199, 299]

        const float4* gB = reinterpret_cast<const float4*>(g_blankD + b * ND_ * DW_);
        const float4* gE = reinterpret_cast<const float4*>(g_emitD  + b * ND_ * DW_);
        float4* sB = reinterpret_cast<float4*>(Bs);
        float4* sE = reinterpret_cast<float4*>(Es);
        volatile int* cnt = g_cnt + b * ND_;

        const int ubase = lane << 2;
        float a0 = 0.f, a1 = NEGV, a2 = NEGV, a3 = NEGV;
        a0 = (lane == 0) ? 0.0f : NEGV;
        float res = NEGV;
        const int slot = llen & 3;

        #pragma unroll 1
        for (int p = 0; p < NPH_; ++p) {
            const int r0 = p * PH_;
            if (r0 + 1 > dstar) break;            // uniform across block
            const int nr = ((ND_ - 1) - r0 < PH_) ? ((ND_ - 1) - r0) : PH_;

            // Wait until all live rows [r0, r0+nr) of this batch are written.
            for (int r = r0 + tid; r < r0 + nr; r += 256) {
                const int need = live_count(r, alen, llen);
                if (need > 0)
                    while (cnt[r] < need) __nanosleep(128);
            }
            __syncthreads();
            __threadfence();                      // acquire before data reads

            // Stage rows [r0, r0+nr), masked + log2-scaled.
            {
                const int n4 = nr * DW4_;
                for (int i = tid; i < n4; i += 256) {
                    const int rr = i / DW4_;
                    const int cc = i - rr * DW4_;
                    const int r  = r0 + rr;
                    stage_row4(gB[r * DW4_ + cc], gE[r * DW4_ + cc],
                               r, cc * 4, alen, llen, &sB[i], &sE[i]);
                }
            }
            __syncthreads();

            if (tid < 32) {
                const int dhi = (r0 + nr < dstar) ? (r0 + nr) : dstar;
                int off = ubase;
                float4 bl = *reinterpret_cast<const float4*>(Bs + off);
                float4 em = *reinterpret_cast<const float4*>(Es + off);
                for (int d = r0 + 1; d <= dhi; ++d) {
                    const float am1 = __shfl_up_sync(0xffffffffu, a3, 1);
                    const float4 cb = bl, ce = em;
                    off += DW_;                   // prefetch next row
                    bl = *reinterpret_cast<const float4*>(Bs + off);
                    em = *reinterpret_cast<const float4*>(Es + off);
                    const float t0 = a0 + cb.x, t1 = a1 + cb.y;
                    const float t2 = a2 + cb.z, t3 = a3 + cb.w;
                    const float l0 = am1 + ce.x, l1 = a0 + ce.y;
                    const float l2 = a1 + ce.z,  l3 = a2 + ce.w;
                    const float x0 = fmaxf(t0, l0), x1 = fmaxf(t1, l1);
                    const float x2 = fmaxf(t2, l2), x3 = fmaxf(t3, l3);
                    const float d0 = fminf(t0, l0) - x0, d1 = fminf(t1, l1) - x1;
                    const float d2 = fminf(t2, l2) - x2, d3 = fminf(t3, l3) - x3;
                    const float g0 = ex2f_(d0), g1 = ex2f_(d1);
                    const float g2 = ex2f_(d2), g3 = ex2f_(d3);
                    a0 = x0 + lg2f_(1.0f + g0);
                    a1 = x1 + lg2f_(1.0f + g1);
                    a2 = x2 + lg2f_(1.0f + g2);
                    a3 = x3 + lg2f_(1.0f + g3);
                    if (d == dstar)
                        res = (slot == 0) ? a0 : (slot == 1) ? a1
                            : (slot == 2) ? a2 : a3;
                }
            }
            __syncthreads();
        }

        // Wait for row dstar (final blank), then finish.
        if (tid == 0) {
            const int need = live_count(dstar, alen, llen);
            while (cnt[dstar] < need) __nanosleep(128);
        }
        __syncthreads();
        __threadfence();

        if (tid < 32) {
            const float rv = __shfl_sync(0xffffffffu, res, llen >> 2);
            if (lane == 0) {
                const float fb = g_blankD[b * ND_ * DW_ + dstar * DW_ + llen];
                g_cost[b] = -(rv * LN2_ + fb);
                __threadfence();
                const int prev = atomicAdd(&g_done, 1);
                if (prev == NDPB_ - 1) {
                    __threadfence();
                    float s = 0.0f;
                    #pragma unroll
                    for (int i = 0; i < B_; ++i) s += g_cost[i];
                    out[0] = s / (float)B_;
                }
            }
        }
        return;
    }

    // ================= softmax producer blocks =================
    // Diagonal-major warp order: w -> (d, u, b).
    const int w = (blockIdx.x - NDPB_) * 8 + (threadIdx.x >> 5);
    const int lane = threadIdx.x & 31;
    if (w >= ND_ * U1_ * B_) return;

    const int b = w % B_;
    const int q = w / B_;
    const int u = q % U1_;
    const int d = q / U1_;
    const int t = d - u;
    if (t < 0 || t >= T_) return;

    const int alen = act_lens[b];
    const int llen = label_lens[b];
    if (t >= alen || u > llen) return;

    const float4* __restrict__ p = reinterpret_cast<const float4*>(
        acts + ((size_t)(b * T_ + t) * U1_ + u) * V_);
    float4 v0 = __ldcs(p + lane);
    float4 v1 = __ldcs(p + lane + 32);
    float4 v2 = __ldcs(p + lane + 64);
    float4 v3 = __ldcs(p + lane + 96);

    float m = fmaxf(fmaxf(fmaxf(v0.x, v0.y), fmaxf(v0.z, v0.w)),
                    fmaxf(fmaxf(v1.x, v1.y), fmaxf(v1.z, v1.w)));
    m = fmaxf(m, fmaxf(fmaxf(fmaxf(v2.x, v2.y), fmaxf(v2.z, v2.w)),
                       fmaxf(fmaxf(v3.x, v3.y), fmaxf(v3.z, v3.w))));
    #pragma unroll
    for (int off = 16; off > 0; off >>= 1)
        m = fmaxf(m, __shfl_xor_sync(0xffffffffu, m, off));

    float s = __expf(v0.x - m) + __expf(v0.y - m) + __expf(v0.z - m) + __expf(v0.w - m)
            + __expf(v1.x - m) + __expf(v1.y - m) + __expf(v1.z - m) + __expf(v1.w - m)
            + __expf(v2.x - m) + __expf(v2.y - m) + __expf(v2.z - m) + __expf(v2.w - m)
            + __expf(v3.x - m) + __expf(v3.y - m) + __expf(v3.z - m) + __expf(v3.w - m);
    #pragma unroll
    for (int off = 16; off > 0; off >>= 1)
        s += __shfl_xor_sync(0xffffffffu, s, off);

    const float lse = m + __logf(s);
    const float blank_logit = __shfl_sync(0xffffffffu, v0.x, 0);

    int lbl = 0;
    if (u < U_) lbl = labels[b * U_ + u];
    const int jj  = lbl >> 2;
    const int src = jj & 31;
    const int k   = jj >> 5;
    const int c   = lbl & 3;
    float4 sel = (k == 0) ? v0 : (k == 1) ? v1 : (k == 2) ? v2 : v3;
    float cand = (c == 0) ? sel.x : (c == 1) ? sel.y : (c == 2) ? sel.z : sel.w;
    const float label_logit = __shfl_sync(0xffffffffu, cand, src);

    if (lane == 0) {
        const int base = b * ND_ * DW_ + d * DW_;
        g_blankD[base + u] = blank_logit - lse;
        if (u < llen)
            g_emitD[base + u + 1] = label_logit - lse;
        __threadfence();                      // release before counter bump
        atomicAdd(&g_cnt[b * ND_ + d], 1);
    }
}

// ---------------------------------------------------------------------------
extern "C" void kernel_launch(void* const* d_in, const int* in_sizes, int n_in,
                              void* d_out, int out_size)
{
    const float* acts       = (const float*)d_in[0];
    const int*   labels     = (const int*)  d_in[1];
    const int*   act_lens   = (const int*)  d_in[2];
    const int*   label_lens = (const int*)  d_in[3];
    float*       out        = (float*)      d_out;

    // Kernel 0: zero sync counters (graph-replay safe).
    rnnt_init_kernel<<<(B_ * ND_ + 255) / 256, 256>>>();

    // Fused producer/consumer kernel.
    const int wtot    = ND_ * U1_ * B_;            // 484,800 softmax warps
    const int sblocks = (wtot + 7) / 8;            // 60,600
    rnnt_fused_kernel<<<NDPB_ + sblocks, 256>>>(acts, labels, act_lens,
                                                label_lens, out);
}

// round 17
// speedup vs baseline: 1.2834x; 1.0420x over previous
#include <cuda_runtime.h>

#define B_   16
#define T_   200
#define U1_  101
#define U_   100
#define V_   512
#define ND_  300          /* time-diagonals: d = t+u in [0, 299] */
#define DW_  104          /* padded diagonal width (u slots), 26 float4 */
#define DW4_ 26
#define PH_  19           /* diagonal rows staged per phase */
#define NPH_ 16           /* 16*19 = 304 >= 299 */
#define PAD_ 128          /* guard pad (floats): prefetch + lane overread */
#define RS_  (PH_ * DW_ + PAD_)   /* region stride: 2104 floats */
#define NDPB_ 16          /* DP blocks (first in grid) */
#define NEGV   (-1e30f)
#define LOG2E_ 1.4426950408889634f
#define LN2_   0.6931471805599453f

// Diagonal-major scratch (natural-log): [b][d][u]. emitD shifted (+1 in u) so
// cell (d,u)'s deps both sit at row d-1, slot u. Dead slots = stale garbage;
// the DP staging mask replaces them with NEGV by pure coordinate tests.
__device__ float g_blankD[B_ * ND_ * DW_];
__device__ float g_emitD [B_ * ND_ * DW_];
__device__ int   g_cnt   [B_ * T_];       // warps completed per (b, t-row)
__device__ volatile float g_cost[B_];
__device__ int   g_done;

__device__ __forceinline__ float ex2f_(float x) {
    float r; asm("ex2.approx.ftz.f32 %0, %1;" : "=f"(r) : "f"(x)); return r;
}
__device__ __forceinline__ float lg2f_(float x) {
    float r; asm("lg2.approx.ftz.f32 %0, %1;" : "=f"(r) : "f"(x)); return r;
}

// ---------------------------------------------------------------------------
// Kernel 0: zero the sync state for each graph replay.
// ---------------------------------------------------------------------------
__global__ void rnnt_init_kernel()
{
    const int i = blockIdx.x * blockDim.x + threadIdx.x;
    if (i < B_ * T_) g_cnt[i] = 0;
    if (i == 0) g_done = 0;
}

// ---------------------------------------------------------------------------
// Masked staging: NEGV for coordinate-invalid slots; valid -> log2 domain.
// ---------------------------------------------------------------------------
__device__ __forceinline__ void stage_row4(
    float4 xb, float4 xe, int r, int v0, int alen, int llen,
    float4* outB, float4* outE)
{
    float bb[4] = { xb.x, xb.y, xb.z, xb.w };
    float ee[4] = { xe.x, xe.y, xe.z, xe.w };
    #pragma unroll
    for (int k = 0; k < 4; ++k) {
        const int v = v0 + k;
        const bool bv = (v <= llen) && (v <= r)     && (r - v     <= alen - 1);
        const bool ev = (v >= 1) && (v <= llen) && (v <= r + 1) && (r - v + 1 <= alen - 1);
        bb[k] = bv ? (bb[k] * LOG2E_) : NEGV;
        ee[k] = ev ? (ee[k] * LOG2E_) : NEGV;
    }
    *outB = make_float4(bb[0], bb[1], bb[2], bb[3]);
    *outE = make_float4(ee[0], ee[1], ee[2], ee[3]);
}

// ---------------------------------------------------------------------------
// Fused kernel.  Blocks [0, NDPB_): persistent per-batch DP consumers.
// Blocks [NDPB_, ...): log-softmax producers in T-OUTERMOST order
// (w -> t, b, u with u innermost), which keeps DRAM reads streaming
// (contiguous 2KB rows) while still completing all diagonal rows <= r
// as soon as t-rows <= r are done.
// ---------------------------------------------------------------------------
__global__ void __launch_bounds__(256) rnnt_fused_kernel(
    const float* __restrict__ acts,
    const int*   __restrict__ labels,
    const int*   __restrict__ act_lens,
    const int*   __restrict__ label_lens,
    float* __restrict__ out)
{
    // ================= DP consumer blocks =================
    if (blockIdx.x < NDPB_) {
        __shared__ float Bs[RS_];
        __shared__ float Es[RS_];

        const int b    = blockIdx.x;
        const int tid  = threadIdx.x;
        const int lane = tid & 31;

        const int alen  = act_lens[b];
        const int llen  = label_lens[b];
        const int dstar = (alen - 1) + llen;      // in [199, 299]
        const int rowneed = llen + 1;             // live warps per t-row

        const float4* gB = reinterpret_cast<const float4*>(g_blankD + b * ND_ * DW_);
        const float4* gE = reinterpret_cast<const float4*>(g_emitD  + b * ND_ * DW_);
        float4* sB = reinterpret_cast<float4*>(Bs);
        float4* sE = reinterpret_cast<float4*>(Es);
        volatile int* cnt = g_cnt + b * T_;

        const int ubase = lane << 2;
        float a0 = 0.f, a1 = NEGV, a2 = NEGV, a3 = NEGV;
        a0 = (lane == 0) ? 0.0f : NEGV;
        float res = NEGV;
        const int slot = llen & 3;

        #pragma unroll 1
        for (int p = 0; p < NPH_; ++p) {
            const int r0 = p * PH_;
            if (r0 + 1 > dstar) break;            // uniform across block
            const int nr = ((ND_ - 1) - r0 < PH_) ? ((ND_ - 1) - r0) : PH_;

            // Diagonal rows [r0, r0+nr) only contain cells with t <= r0+nr-1,
            // so wait until softmax t-rows [r0, min(r0+nr-1, alen-1)] are done.
            {
                const int thi = (r0 + nr - 1 < alen - 1) ? (r0 + nr - 1) : (alen - 1);
                for (int r = r0 + tid; r <= thi; r += 256)
                    while (cnt[r] < rowneed) __nanosleep(128);
            }
            __syncthreads();
            __threadfence();                      // acquire before data reads

            // Stage diag rows [r0, r0+nr), masked + log2-scaled.
            {
                const int n4 = nr * DW4_;
                for (int i = tid; i < n4; i += 256) {
                    const int rr = i / DW4_;
                    const int cc = i - rr * DW4_;
                    const int r  = r0 + rr;
                    stage_row4(gB[r * DW4_ + cc], gE[r * DW4_ + cc],
                               r, cc * 4, alen, llen, &sB[i], &sE[i]);
                }
            }
            __syncthreads();

            if (tid < 32) {
                const int dhi = (r0 + nr < dstar) ? (r0 + nr) : dstar;
                int off = ubase;
                float4 bl = *reinterpret_cast<const float4*>(Bs + off);
                float4 em = *reinterpret_cast<const float4*>(Es + off);
                for (int d = r0 + 1; d <= dhi; ++d) {
                    const float am1 = __shfl_up_sync(0xffffffffu, a3, 1);
                    const float4 cb = bl, ce = em;
                    off += DW_;                   // prefetch next row
                    bl = *reinterpret_cast<const float4*>(Bs + off);
                    em = *reinterpret_cast<const float4*>(Es + off);
                    const float t0 = a0 + cb.x, t1 = a1 + cb.y;
                    const float t2 = a2 + cb.z, t3 = a3 + cb.w;
                    const float l0 = am1 + ce.x, l1 = a0 + ce.y;
                    const float l2 = a1 + ce.z,  l3 = a2 + ce.w;
                    const float x0 = fmaxf(t0, l0), x1 = fmaxf(t1, l1);
                    const float x2 = fmaxf(t2, l2), x3 = fmaxf(t3, l3);
                    const float d0 = fminf(t0, l0) - x0, d1 = fminf(t1, l1) - x1;
                    const float d2 = fminf(t2, l2) - x2, d3 = fminf(t3, l3) - x3;
                    const float g0 = ex2f_(d0), g1 = ex2f_(d1);
                    const float g2 = ex2f_(d2), g3 = ex2f_(d3);
                    a0 = x0 + lg2f_(1.0f + g0);
                    a1 = x1 + lg2f_(1.0f + g1);
                    a2 = x2 + lg2f_(1.0f + g2);
                    a3 = x3 + lg2f_(1.0f + g3);
                    if (d == dstar)
                        res = (slot == 0) ? a0 : (slot == 1) ? a1
                            : (slot == 2) ? a2 : a3;
                }
            }
            __syncthreads();
        }

        // Final blank lives at (alen-1, llen): wait for its t-row, then finish.
        if (tid == 0)
            while (cnt[alen - 1] < rowneed) __nanosleep(128);
        __syncthreads();
        __threadfence();

        if (tid < 32) {
            const float rv = __shfl_sync(0xffffffffu, res, llen >> 2);
            if (lane == 0) {
                const float fb = g_blankD[b * ND_ * DW_ + dstar * DW_ + llen];
                g_cost[b] = -(rv * LN2_ + fb);
                __threadfence();
                const int prev = atomicAdd(&g_done, 1);
                if (prev == NDPB_ - 1) {
                    __threadfence();
                    float s = 0.0f;
                    #pragma unroll
                    for (int i = 0; i < B_; ++i) s += g_cost[i];
                    out[0] = s / (float)B_;
                }
            }
        }
        return;
    }

    // ================= softmax producer blocks =================
    // T-outermost warp order: w -> (t, b, u), u innermost (streaming reads).
    const int w = (blockIdx.x - NDPB_) * 8 + (threadIdx.x >> 5);
    const int lane = threadIdx.x & 31;
    if (w >= T_ * B_ * U1_) return;

    const int u   = w % U1_;
    const int rem = w / U1_;
    const int b   = rem % B_;
    const int t   = rem / B_;

    const int alen = act_lens[b];
    const int llen = label_lens[b];
    if (t >= alen || u > llen) return;

    const float4* __restrict__ p = reinterpret_cast<const float4*>(
        acts + ((size_t)(b * T_ + t) * U1_ + u) * V_);
    float4 v0 = __ldcs(p + lane);
    float4 v1 = __ldcs(p + lane + 32);
    float4 v2 = __ldcs(p + lane + 64);
    float4 v3 = __ldcs(p + lane + 96);

    float m = fmaxf(fmaxf(fmaxf(v0.x, v0.y), fmaxf(v0.z, v0.w)),
                    fmaxf(fmaxf(v1.x, v1.y), fmaxf(v1.z, v1.w)));
    m = fmaxf(m, fmaxf(fmaxf(fmaxf(v2.x, v2.y), fmaxf(v2.z, v2.w)),
                       fmaxf(fmaxf(v3.x, v3.y), fmaxf(v3.z, v3.w))));
    #pragma unroll
    for (int off = 16; off > 0; off >>= 1)
        m = fmaxf(m, __shfl_xor_sync(0xffffffffu, m, off));

    float s = __expf(v0.x - m) + __expf(v0.y - m) + __expf(v0.z - m) + __expf(v0.w - m)
            + __expf(v1.x - m) + __expf(v1.y - m) + __expf(v1.z - m) + __expf(v1.w - m)
            + __expf(v2.x - m) + __expf(v2.y - m) + __expf(v2.z - m) + __expf(v2.w - m)
            + __expf(v3.x - m) + __expf(v3.y - m) + __expf(v3.z - m) + __expf(v3.w - m);
    #pragma unroll
    for (int off = 16; off > 0; off >>= 1)
        s += __shfl_xor_sync(0xffffffffu, s, off);

    const float lse = m + __logf(s);
    const float blank_logit = __shfl_sync(0xffffffffu, v0.x, 0);

    int lbl = 0;
    if (u < U_) lbl = labels[b * U_ + u];
    const int jj  = lbl >> 2;
    const int src = jj & 31;
    const int k   = jj >> 5;
    const int c   = lbl & 3;
    float4 sel = (k == 0) ? v0 : (k == 1) ? v1 : (k == 2) ? v2 : v3;
    float cand = (c == 0) ? sel.x : (c == 1) ? sel.y : (c == 2) ? sel.z : sel.w;
    const float label_logit = __shfl_sync(0xffffffffu, cand, src);

    if (lane == 0) {
        const int d    = t + u;
        const int base = b * ND_ * DW_ + d * DW_;
        g_blankD[base + u] = blank_logit - lse;
        if (u < llen)
            g_emitD[base + u + 1] = label_logit - lse;
        __threadfence();                      // release before counter bump
        atomicAdd(&g_cnt[b * T_ + t], 1);
    }
}

// ---------------------------------------------------------------------------
extern "C" void kernel_launch(void* const* d_in, const int* in_sizes, int n_in,
                              void* d_out, int out_size)
{
    const float* acts       = (const float*)d_in[0];
    const int*   labels     = (const int*)  d_in[1];
    const int*   act_lens   = (const int*)  d_in[2];
    const int*   label_lens = (const int*)  d_in[3];
    float*       out        = (float*)      d_out;

    // Kernel 0: zero sync counters (graph-replay safe).
    rnnt_init_kernel<<<(B_ * T_ + 255) / 256, 256>>>();

    // Fused producer/consumer kernel.
    const int wtot    = T_ * B_ * U1_;             // 323,200 softmax warps
    const int sblocks = (wtot + 7) / 8;            // 40,400
    rnnt_fused_kernel<<<NDPB_ + sblocks, 256>>>(acts, labels, act_lens,
                                                label_lens, out);
}